// round 10
// baseline (speedup 1.0000x reference)
#include <cuda_runtime.h>
#include <cstdint>

// out[t, h] = W[h, seq[t]] + b[h]
// seq: int32 [n_tok], W: fp32 [H, V] row-major, b: fp32 [H], out: fp32 [n_tok, H]
//
// Pipeline (4 launches, PDL-overlapped chain):
//  1) hist    : bucket counts of v>>3 (one 32B W sector per bucket)
//  2) scan    : exclusive scan -> g_off; re-zeroes g_hist (zero at load ->
//               deterministic across graph replays).         [PDL]
//  3) scatter : counting-sort packed (v,t) int2 by bucket.    [PDL]
//  4) gather  : TOK_PER_BLK=64 (wider sorted v-window -> ~392B contiguous
//               DRAM runs per (block,h) instead of ~196B), HCHUNK=64 keeps
//               smem at 16.6KB -> 8 blocks/SM. Lanes-along-sorted-v loads,
//               padded-SMEM transpose, coalesced streaming stores. [PDL]

#define H_DIM 1024
#define TOK_PER_BLK 64
#define THREADS 256
#define HCHUNK 64
#define NCHUNK (H_DIM / HCHUNK)   // 16
#define SPAD (TOK_PER_BLK + 1)    // 65: conflict-free both phases

#define MAX_N 65536
#define MAX_BUCKETS 8192
#define SCAN_THREADS 1024
#define SCAN_PER 8                 // 1024*8 = 8192 >= MAX_BUCKETS

__device__ int g_hist[MAX_BUCKETS];   // zero at load; scan re-zeroes after use
__device__ int g_off[MAX_BUCKETS];
__device__ int2 g_sorted[MAX_N];      // .x = v, .y = t

// ---------------- sort pipeline (proven bodies) ----------------

__global__ void hist_kernel(const int* __restrict__ seq, int n) {
    int i = blockIdx.x * blockDim.x + threadIdx.x;
    if (i < n) atomicAdd(&g_hist[seq[i] >> 3], 1);
}

__global__ __launch_bounds__(SCAN_THREADS)
void scan_kernel(int nbuckets) {
    cudaGridDependencySynchronize();   // g_hist ready

    __shared__ int warp_sums[32];
    const int tid  = threadIdx.x;
    const int lane = tid & 31;
    const int w    = tid >> 5;

    int vals[SCAN_PER];
    int local = 0;
    #pragma unroll
    for (int i = 0; i < SCAN_PER; i++) {
        int idx = tid * SCAN_PER + i;
        vals[i] = (idx < nbuckets) ? g_hist[idx] : 0;
        local += vals[i];
    }

    int x = local;
    #pragma unroll
    for (int d = 1; d < 32; d <<= 1) {
        int y = __shfl_up_sync(0xFFFFFFFFu, x, d);
        if (lane >= d) x += y;
    }
    if (lane == 31) warp_sums[w] = x;
    __syncthreads();

    if (w == 0) {
        int s = warp_sums[lane];
        #pragma unroll
        for (int d = 1; d < 32; d <<= 1) {
            int y = __shfl_up_sync(0xFFFFFFFFu, s, d);
            if (lane >= d) s += y;
        }
        warp_sums[lane] = s;
    }
    __syncthreads();

    int run = (w > 0 ? warp_sums[w - 1] : 0) + (x - local);
    #pragma unroll
    for (int i = 0; i < SCAN_PER; i++) {
        int idx = tid * SCAN_PER + i;
        if (idx < nbuckets) {
            g_off[idx]  = run;
            g_hist[idx] = 0;         // leave zeroed for next invocation
        }
        run += vals[i];
    }
}

__global__ void scatter_kernel(const int* __restrict__ seq, int n) {
    int t = blockIdx.x * blockDim.x + threadIdx.x;
    int v = 0;
    if (t < n) v = seq[t];           // independent of scan: before sync

    cudaGridDependencySynchronize(); // g_off ready

    if (t < n) {
        int pos = atomicAdd(&g_off[v >> 3], 1);
        g_sorted[pos] = make_int2(v, t);
    }
}

// ---------------- main gather: 64-token window ----------------

__global__ __launch_bounds__(THREADS, 8)
void onehot_gather_xpose_kernel(const float* __restrict__ W,
                                const float* __restrict__ bias,
                                float* __restrict__ out,
                                int n_tok, int V) {
    __shared__ float s_w[HCHUNK][SPAD];
    __shared__ int s_t[TOK_PER_BLK];
    __shared__ int s_v[TOK_PER_BLK];

    const int tid  = threadIdx.x;
    const int lane = tid & 31;
    const int w    = tid >> 5;
    const int base = blockIdx.x * TOK_PER_BLK;

    cudaGridDependencySynchronize();  // g_sorted ready; overlaps block ramp

    if (tid < TOK_PER_BLK) {
        int j = base + tid;
        int2 vt = (j < n_tok) ? g_sorted[j] : make_int2(0, -1);
        s_v[tid] = vt.x;   // clamped: valid address for padding tokens
        s_t[tid] = vt.y;   // -1 -> skip store
    }
    __syncthreads();

    // Load phase: lane owns tokens 'lane' and 'lane+32' (sorted values ->
    // each warp-LDG's 32 lanes collapse to few contiguous sectors).
    const int my_v0 = s_v[lane];
    const int my_v1 = s_v[lane + 32];

    // Store phase: warp w owns tokens 8w..8w+7.
    int st_t[8];
    #pragma unroll
    for (int q = 0; q < 8; q++) st_t[q] = s_t[(w << 3) + q];

    const size_t Vs = (size_t)V;

    for (int c = 0; c < NCHUNK; c++) {
        const int h_base = c * HCHUNK;

        // ---- load phase: 16 independent gathers per thread ----
        #pragma unroll
        for (int i = 0; i < 8; i++) {
            int h_local = (i << 3) + w;          // warp w covers w, w+8, ...
            const float* Wr = W + (size_t)(h_base + h_local) * Vs;
            s_w[h_local][lane]      = __ldg(Wr + my_v0);  // tokens 0..31
            s_w[h_local][lane + 32] = __ldg(Wr + my_v1);  // tokens 32..63
        }

        // bias for this lane's 2 h positions in the chunk
        float bl0 = __ldg(bias + h_base + lane);
        float bl1 = __ldg(bias + h_base + 32 + lane);

        __syncthreads();

        // ---- store phase: coalesced 128B rows ----
        #pragma unroll
        for (int q = 0; q < 8; q++) {
            const int j = (w << 3) + q;
            const int t = st_t[q];
            if (t < 0) continue;
            float* dst = out + (size_t)t * H_DIM + h_base;
            __stcs(dst + lane,      s_w[lane][j]      + bl0);  // stride-65: ok
            __stcs(dst + 32 + lane, s_w[lane + 32][j] + bl1);
        }
        __syncthreads();
    }
}

// ---------------- launch (PDL on the dependency chain) ----------------

template <typename Kern, typename... Args>
static void launch_pdl(Kern k, dim3 grid, dim3 block, Args... args) {
    cudaLaunchConfig_t cfg = {};
    cfg.gridDim  = grid;
    cfg.blockDim = block;
    cfg.dynamicSmemBytes = 0;
    cudaLaunchAttribute attr[1];
    attr[0].id = cudaLaunchAttributeProgrammaticStreamSerialization;
    attr[0].val.programmaticStreamSerializationAllowed = 1;
    cfg.attrs = attr;
    cfg.numAttrs = 1;
    cudaLaunchKernelEx(&cfg, k, args...);
}

extern "C" void kernel_launch(void* const* d_in, const int* in_sizes, int n_in,
                              void* d_out, int out_size) {
    const int*   seq  = (const int*)d_in[0];
    const float* W    = (const float*)d_in[1];
    const float* bias = (const float*)d_in[2];
    float*       out  = (float*)d_out;

    const int n_tok = in_sizes[0];            // 32768
    const int H     = in_sizes[2];            // 1024
    const int V     = in_sizes[1] / H;        // 50257
    const int nbuckets = (V + 7) >> 3;        // 6283
    (void)out_size; (void)n_in;

    hist_kernel<<<(n_tok + 255) / 256, 256>>>(seq, n_tok);

    launch_pdl(scan_kernel, dim3(1), dim3(SCAN_THREADS), nbuckets);
    launch_pdl(scatter_kernel, dim3((n_tok + 255) / 256), dim3(256), seq, n_tok);

    const int blocks = (n_tok + TOK_PER_BLK - 1) / TOK_PER_BLK;
    launch_pdl(onehot_gather_xpose_kernel, dim3(blocks), dim3(THREADS),
               W, bias, out, n_tok, V);
}

// round 11
// speedup vs baseline: 1.0154x; 1.0154x over previous
#include <cuda_runtime.h>
#include <cstdint>

// out[t, h] = W[h, seq[t]] + b[h]
// seq: int32 [n_tok], W: fp32 [H, V] row-major, b: fp32 [H], out: fp32 [n_tok, H]
//
// Pipeline (4 launches, PDL-overlapped chain):
//  1) hist    : bucket counts of v>>3
//  2) scan    : exclusive scan -> g_off; re-zeroes g_hist.      [PDL]
//  3) scatter : counting-sort packed (v,t) int2 by bucket.      [PDL]
//  4) gather  : 64-token sorted window (2x longer contiguous DRAM runs than
//               R9) x 512-h half per block; grid = 512x2 = 1024 blocks so
//               occupancy stays ~84% (R10 lesson: grid >= ~1184 block-slots).
//               Lanes-along-sorted-v loads, padded-SMEM transpose, coalesced
//               streaming stores.                                [PDL]

#define H_DIM 1024
#define TOK_PER_BLK 64
#define THREADS 256
#define HCHUNK 64
#define H_PER_BLK 512
#define NCHUNK (H_PER_BLK / HCHUNK)  // 8
#define SPAD (TOK_PER_BLK + 1)       // 65: conflict-free both phases

#define MAX_N 65536
#define MAX_BUCKETS 8192
#define SCAN_THREADS 1024
#define SCAN_PER 8                    // 1024*8 = 8192 >= MAX_BUCKETS

__device__ int g_hist[MAX_BUCKETS];   // zero at load; scan re-zeroes after use
__device__ int g_off[MAX_BUCKETS];
__device__ int2 g_sorted[MAX_N];      // .x = v, .y = t

// ---------------- sort pipeline (proven bodies) ----------------

__global__ void hist_kernel(const int* __restrict__ seq, int n) {
    int i = blockIdx.x * blockDim.x + threadIdx.x;
    if (i < n) atomicAdd(&g_hist[seq[i] >> 3], 1);
}

__global__ __launch_bounds__(SCAN_THREADS)
void scan_kernel(int nbuckets) {
    cudaGridDependencySynchronize();   // g_hist ready

    __shared__ int warp_sums[32];
    const int tid  = threadIdx.x;
    const int lane = tid & 31;
    const int w    = tid >> 5;

    int vals[SCAN_PER];
    int local = 0;
    #pragma unroll
    for (int i = 0; i < SCAN_PER; i++) {
        int idx = tid * SCAN_PER + i;
        vals[i] = (idx < nbuckets) ? g_hist[idx] : 0;
        local += vals[i];
    }

    int x = local;
    #pragma unroll
    for (int d = 1; d < 32; d <<= 1) {
        int y = __shfl_up_sync(0xFFFFFFFFu, x, d);
        if (lane >= d) x += y;
    }
    if (lane == 31) warp_sums[w] = x;
    __syncthreads();

    if (w == 0) {
        int s = warp_sums[lane];
        #pragma unroll
        for (int d = 1; d < 32; d <<= 1) {
            int y = __shfl_up_sync(0xFFFFFFFFu, s, d);
            if (lane >= d) s += y;
        }
        warp_sums[lane] = s;
    }
    __syncthreads();

    int run = (w > 0 ? warp_sums[w - 1] : 0) + (x - local);
    #pragma unroll
    for (int i = 0; i < SCAN_PER; i++) {
        int idx = tid * SCAN_PER + i;
        if (idx < nbuckets) {
            g_off[idx]  = run;
            g_hist[idx] = 0;         // leave zeroed for next invocation
        }
        run += vals[i];
    }
}

__global__ void scatter_kernel(const int* __restrict__ seq, int n) {
    int t = blockIdx.x * blockDim.x + threadIdx.x;
    int v = 0;
    if (t < n) v = seq[t];           // independent of scan: before sync

    cudaGridDependencySynchronize(); // g_off ready

    if (t < n) {
        int pos = atomicAdd(&g_off[v >> 3], 1);
        g_sorted[pos] = make_int2(v, t);
    }
}

// ---------------- main gather: 64-token window x 512-h half ----------------

__global__ __launch_bounds__(THREADS, 8)
void onehot_gather_xpose_kernel(const float* __restrict__ W,
                                const float* __restrict__ bias,
                                float* __restrict__ out,
                                int n_tok, int V) {
    __shared__ float s_w[HCHUNK][SPAD];
    __shared__ int s_t[TOK_PER_BLK];
    __shared__ int s_v[TOK_PER_BLK];

    const int tid  = threadIdx.x;
    const int lane = tid & 31;
    const int w    = tid >> 5;
    const int base    = blockIdx.x * TOK_PER_BLK;  // token window
    const int h_block = blockIdx.y * H_PER_BLK;    // h half

    cudaGridDependencySynchronize();  // g_sorted ready; overlaps block ramp

    if (tid < TOK_PER_BLK) {
        int j = base + tid;
        int2 vt = (j < n_tok) ? g_sorted[j] : make_int2(0, -1);
        s_v[tid] = vt.x;   // clamped: valid address for padding tokens
        s_t[tid] = vt.y;   // -1 -> skip store
    }
    __syncthreads();

    // Load phase: lane owns tokens 'lane' and 'lane+32' (sorted values ->
    // each warp-LDG's 32 lanes collapse to few contiguous sectors).
    const int my_v0 = s_v[lane];
    const int my_v1 = s_v[lane + 32];

    // Store phase: warp w owns tokens 8w..8w+7.
    int st_t[8];
    #pragma unroll
    for (int q = 0; q < 8; q++) st_t[q] = s_t[(w << 3) + q];

    const size_t Vs = (size_t)V;

    for (int c = 0; c < NCHUNK; c++) {
        const int h_base = h_block + c * HCHUNK;

        // ---- load phase: 16 independent gathers per thread ----
        #pragma unroll
        for (int i = 0; i < 8; i++) {
            int h_local = (i << 3) + w;          // warp w covers w, w+8, ...
            const float* Wr = W + (size_t)(h_base + h_local) * Vs;
            s_w[h_local][lane]      = __ldg(Wr + my_v0);  // tokens 0..31
            s_w[h_local][lane + 32] = __ldg(Wr + my_v1);  // tokens 32..63
        }

        // bias for this lane's 2 h positions in the chunk
        float bl0 = __ldg(bias + h_base + lane);
        float bl1 = __ldg(bias + h_base + 32 + lane);

        __syncthreads();

        // ---- store phase: coalesced 128B rows ----
        #pragma unroll
        for (int q = 0; q < 8; q++) {
            const int j = (w << 3) + q;
            const int t = st_t[q];
            if (t < 0) continue;
            float* dst = out + (size_t)t * H_DIM + h_base;
            __stcs(dst + lane,      s_w[lane][j]      + bl0);  // stride-65: ok
            __stcs(dst + 32 + lane, s_w[lane + 32][j] + bl1);
        }
        __syncthreads();
    }
}

// ---------------- launch (PDL on the dependency chain) ----------------

template <typename Kern, typename... Args>
static void launch_pdl(Kern k, dim3 grid, dim3 block, Args... args) {
    cudaLaunchConfig_t cfg = {};
    cfg.gridDim  = grid;
    cfg.blockDim = block;
    cfg.dynamicSmemBytes = 0;
    cudaLaunchAttribute attr[1];
    attr[0].id = cudaLaunchAttributeProgrammaticStreamSerialization;
    attr[0].val.programmaticStreamSerializationAllowed = 1;
    cfg.attrs = attr;
    cfg.numAttrs = 1;
    cudaLaunchKernelEx(&cfg, k, args...);
}

extern "C" void kernel_launch(void* const* d_in, const int* in_sizes, int n_in,
                              void* d_out, int out_size) {
    const int*   seq  = (const int*)d_in[0];
    const float* W    = (const float*)d_in[1];
    const float* bias = (const float*)d_in[2];
    float*       out  = (float*)d_out;

    const int n_tok = in_sizes[0];            // 32768
    const int H     = in_sizes[2];            // 1024
    const int V     = in_sizes[1] / H;        // 50257
    const int nbuckets = (V + 7) >> 3;        // 6283
    (void)out_size; (void)n_in;

    hist_kernel<<<(n_tok + 255) / 256, 256>>>(seq, n_tok);

    launch_pdl(scan_kernel, dim3(1), dim3(SCAN_THREADS), nbuckets);
    launch_pdl(scatter_kernel, dim3((n_tok + 255) / 256), dim3(256), seq, n_tok);

    const int tgroups = (n_tok + TOK_PER_BLK - 1) / TOK_PER_BLK;  // 512
    launch_pdl(onehot_gather_xpose_kernel,
               dim3(tgroups, H_DIM / H_PER_BLK), dim3(THREADS),
               W, bias, out, n_tok, V);
}

// round 12
// speedup vs baseline: 1.2208x; 1.2023x over previous
#include <cuda_runtime.h>
#include <cstdint>

// out[t, h] = W[h, seq[t]] + b[h]
// seq: int32 [n_tok], W: fp32 [H, V] row-major, b: fp32 [H], out: fp32 [n_tok, H]
//
// Pipeline (4 launches, PDL-overlapped chain):
//  1) hist    : bucket counts of v>>3
//  2) scan    : exclusive scan -> g_off (padded to mult of 4 with total);
//               re-zeroes g_hist.                                [PDL]
//  3) scatter : counting-sort packed (v,t) int2 by bucket; post-increment
//               turns g_off[b] into bucket-END offsets.          [PDL]
//  4) gather  : block k owns vocab range [32k,32k+32). W loads are ONE
//               fully coalesced 128B LDG per h-row (1 L1 wavefront, W swept
//               exactly once, sequentially). Tokens of the range = sorted
//               slice [g_off[4k-1], g_off[4k+3]). Padded-SMEM transpose,
//               coalesced streaming stores.                      [PDL]

#define H_DIM 1024
#define THREADS 256
#define VRANGE 32                  // values per block = 128B per h-row
#define HCHUNK 128
#define NCHUNK (H_DIM / HCHUNK)    // 8
#define SPAD 33                    // pad -> conflict-free transpose reads
#define TBUF 192                   // token buffer (mean ~21, P(>192) ~ 0)

#define MAX_N 65536
#define MAX_BUCKETS 8192
#define SCAN_THREADS 1024
#define SCAN_PER 8                 // 1024*8 = 8192 >= MAX_BUCKETS

__device__ int g_hist[MAX_BUCKETS];   // zero at load; scan re-zeroes after use
__device__ int g_off[MAX_BUCKETS];    // after scatter: bucket END offsets
__device__ int2 g_sorted[MAX_N];      // .x = v, .y = t

// ---------------- sort pipeline (proven bodies) ----------------

__global__ void hist_kernel(const int* __restrict__ seq, int n) {
    int i = blockIdx.x * blockDim.x + threadIdx.x;
    if (i < n) atomicAdd(&g_hist[seq[i] >> 3], 1);
}

__global__ __launch_bounds__(SCAN_THREADS)
void scan_kernel(int nbuckets) {
    cudaGridDependencySynchronize();   // g_hist ready

    __shared__ int warp_sums[32];
    const int tid  = threadIdx.x;
    const int lane = tid & 31;
    const int w    = tid >> 5;
    const int nbuckets_pad = (nbuckets + 3) & ~3;  // cover block 1570's end

    int vals[SCAN_PER];
    int local = 0;
    #pragma unroll
    for (int i = 0; i < SCAN_PER; i++) {
        int idx = tid * SCAN_PER + i;
        vals[i] = (idx < nbuckets) ? g_hist[idx] : 0;
        local += vals[i];
    }

    int x = local;
    #pragma unroll
    for (int d = 1; d < 32; d <<= 1) {
        int y = __shfl_up_sync(0xFFFFFFFFu, x, d);
        if (lane >= d) x += y;
    }
    if (lane == 31) warp_sums[w] = x;
    __syncthreads();

    if (w == 0) {
        int s = warp_sums[lane];
        #pragma unroll
        for (int d = 1; d < 32; d <<= 1) {
            int y = __shfl_up_sync(0xFFFFFFFFu, s, d);
            if (lane >= d) s += y;
        }
        warp_sums[lane] = s;
    }
    __syncthreads();

    int run = (w > 0 ? warp_sums[w - 1] : 0) + (x - local);
    #pragma unroll
    for (int i = 0; i < SCAN_PER; i++) {
        int idx = tid * SCAN_PER + i;
        if (idx < nbuckets_pad) {
            g_off[idx]  = run;       // pad entries get the running total
            g_hist[idx] = 0;         // leave zeroed for next invocation
        }
        run += vals[i];
    }
}

__global__ void scatter_kernel(const int* __restrict__ seq, int n) {
    int t = blockIdx.x * blockDim.x + threadIdx.x;
    int v = 0;
    if (t < n) v = seq[t];           // independent of scan: before sync

    cudaGridDependencySynchronize(); // g_off ready

    if (t < n) {
        int pos = atomicAdd(&g_off[v >> 3], 1);
        g_sorted[pos] = make_int2(v, t);
    }
}

// ---------------- main gather: fixed vocab ranges ----------------

__global__ __launch_bounds__(THREADS, 8)
void onehot_gather_vrange_kernel(const float* __restrict__ W,
                                 const float* __restrict__ bias,
                                 float* __restrict__ out,
                                 int n_tok, int V) {
    __shared__ float s_w[HCHUNK][SPAD];
    __shared__ int s_o[TBUF];   // value offset within range [0, VRANGE)
    __shared__ int s_t[TBUF];   // original token index

    const int tid   = threadIdx.x;
    const int lane  = tid & 31;
    const int w     = tid >> 5;
    const int k     = blockIdx.x;
    const int vbase = k * VRANGE;

    cudaGridDependencySynchronize();  // g_off/g_sorted ready

    // token slice for this vocab range: buckets 4k .. 4k+3
    const int b0 = k << 2;
    const int t0 = (k > 0) ? g_off[b0 - 1] : 0;
    const int t1 = g_off[b0 + 3];

    const size_t Vs = (size_t)V;
    const int v = vbase + lane;
    const bool v_ok = (v < V);

    for (int tp = t0; tp < t1; tp += TBUF) {  // 1 pass in practice
        const int cnt = min(t1 - tp, TBUF);

        __syncthreads();  // protect s_o/s_t against the previous pass
        for (int j = tid; j < cnt; j += THREADS) {
            int2 vt = g_sorted[tp + j];
            s_o[j] = vt.x - vbase;
            s_t[j] = vt.y;
        }
        __syncthreads();

        for (int c = 0; c < NCHUNK; c++) {
            const int h_base = c * HCHUNK;

            // ---- load: ONE coalesced 128B LDG per h-row, 16 rows/warp ----
            #pragma unroll
            for (int i = 0; i < 16; i++) {
                int hl = (i << 3) + w;       // warp w covers hl = w, w+8, ...
                float val = v_ok ? __ldg(W + (size_t)(h_base + hl) * Vs + v) : 0.0f;
                s_w[hl][lane] = val;         // stride-1 across lanes
            }

            float bl[4];
            #pragma unroll
            for (int hs = 0; hs < 4; hs++)
                bl[hs] = __ldg(bias + h_base + (hs << 5) + lane);

            __syncthreads();

            // ---- store: warp per token, coalesced 128B rows ----
            for (int j = w; j < cnt; j += 8) {
                const int o = s_o[j];
                float* dst = out + (size_t)s_t[j] * H_DIM + h_base;
                #pragma unroll
                for (int hs = 0; hs < 4; hs++) {
                    int hl = (hs << 5) + lane;
                    __stcs(dst + hl, s_w[hl][o] + bl[hs]);  // LDS stride-33: ok
                }
            }
            __syncthreads();
        }
    }
}

// ---------------- launch (PDL on the dependency chain) ----------------

template <typename Kern, typename... Args>
static void launch_pdl(Kern k, dim3 grid, dim3 block, Args... args) {
    cudaLaunchConfig_t cfg = {};
    cfg.gridDim  = grid;
    cfg.blockDim = block;
    cfg.dynamicSmemBytes = 0;
    cudaLaunchAttribute attr[1];
    attr[0].id = cudaLaunchAttributeProgrammaticStreamSerialization;
    attr[0].val.programmaticStreamSerializationAllowed = 1;
    cfg.attrs = attr;
    cfg.numAttrs = 1;
    cudaLaunchKernelEx(&cfg, k, args...);
}

extern "C" void kernel_launch(void* const* d_in, const int* in_sizes, int n_in,
                              void* d_out, int out_size) {
    const int*   seq  = (const int*)d_in[0];
    const float* W    = (const float*)d_in[1];
    const float* bias = (const float*)d_in[2];
    float*       out  = (float*)d_out;

    const int n_tok = in_sizes[0];            // 32768
    const int H     = in_sizes[2];            // 1024
    const int V     = in_sizes[1] / H;        // 50257
    const int nbuckets = (V + 7) >> 3;        // 6283
    (void)out_size; (void)n_in;

    hist_kernel<<<(n_tok + 255) / 256, 256>>>(seq, n_tok);

    launch_pdl(scan_kernel, dim3(1), dim3(SCAN_THREADS), nbuckets);
    launch_pdl(scatter_kernel, dim3((n_tok + 255) / 256), dim3(256), seq, n_tok);

    const int vblocks = (V + VRANGE - 1) / VRANGE;  // 1571
    launch_pdl(onehot_gather_vrange_kernel, dim3(vblocks), dim3(THREADS),
               W, bias, out, n_tok, V);
}

// round 13
// speedup vs baseline: 1.2358x; 1.0123x over previous
#include <cuda_runtime.h>
#include <cstdint>

// out[t, h] = W[h, seq[t]] + b[h]
// seq: int32 [n_tok], W: fp32 [H, V] row-major, b: fp32 [H], out: fp32 [n_tok, H]
//
// Pipeline (4 launches, PDL-overlapped chain):
//  1) hist    : bucket counts of v>>3
//  2) scan    : exclusive scan -> g_off (padded to mult of 8 with total);
//               re-zeroes g_hist.                                [PDL]
//  3) scatter : counting-sort packed (v,t) int2 by bucket; post-increment
//               turns g_off[b] into bucket-END offsets.          [PDL]
//  4) gather  : block k owns vocab range [64k, 64k+64). Per h-row the load
//               is 256B CONTIGUOUS (two coalesced 128B LDGs, 1 wavefront
//               each). Grid = 786 blocks = single wave (R12 lesson: 1571
//               blocks = 1.33 waves lost 25% to the tail). Tokens of the
//               range = sorted slice over buckets [8k, 8k+8). Padded-SMEM
//               transpose, coalesced streaming stores.           [PDL]

#define H_DIM 1024
#define THREADS 256
#define VRANGE 64                  // values per block = 256B per h-row
#define BPB (VRANGE / 8)           // 8 buckets per block
#define HCHUNK 64
#define NCHUNK (H_DIM / HCHUNK)    // 16
#define SPAD 65                    // pad -> conflict-free transpose reads
#define TBUF 256                   // token buffer (mean ~42, 33-sigma margin)

#define MAX_N 65536
#define MAX_BUCKETS 8192
#define SCAN_THREADS 1024
#define SCAN_PER 8                 // 1024*8 = 8192 >= padded buckets

__device__ int g_hist[MAX_BUCKETS];   // zero at load; scan re-zeroes after use
__device__ int g_off[MAX_BUCKETS];    // after scatter: bucket END offsets
__device__ int2 g_sorted[MAX_N];      // .x = v, .y = t

// ---------------- sort pipeline (proven bodies) ----------------

__global__ void hist_kernel(const int* __restrict__ seq, int n) {
    int i = blockIdx.x * blockDim.x + threadIdx.x;
    if (i < n) atomicAdd(&g_hist[seq[i] >> 3], 1);
}

__global__ __launch_bounds__(SCAN_THREADS)
void scan_kernel(int nbuckets) {
    cudaGridDependencySynchronize();   // g_hist ready

    __shared__ int warp_sums[32];
    const int tid  = threadIdx.x;
    const int lane = tid & 31;
    const int w    = tid >> 5;
    const int nbuckets_pad = (nbuckets + 7) & ~7;  // cover last block's end

    int vals[SCAN_PER];
    int local = 0;
    #pragma unroll
    for (int i = 0; i < SCAN_PER; i++) {
        int idx = tid * SCAN_PER + i;
        vals[i] = (idx < nbuckets) ? g_hist[idx] : 0;
        local += vals[i];
    }

    int x = local;
    #pragma unroll
    for (int d = 1; d < 32; d <<= 1) {
        int y = __shfl_up_sync(0xFFFFFFFFu, x, d);
        if (lane >= d) x += y;
    }
    if (lane == 31) warp_sums[w] = x;
    __syncthreads();

    if (w == 0) {
        int s = warp_sums[lane];
        #pragma unroll
        for (int d = 1; d < 32; d <<= 1) {
            int y = __shfl_up_sync(0xFFFFFFFFu, s, d);
            if (lane >= d) s += y;
        }
        warp_sums[lane] = s;
    }
    __syncthreads();

    int run = (w > 0 ? warp_sums[w - 1] : 0) + (x - local);
    #pragma unroll
    for (int i = 0; i < SCAN_PER; i++) {
        int idx = tid * SCAN_PER + i;
        if (idx < nbuckets_pad) {
            g_off[idx]  = run;       // pad entries get the running total
            g_hist[idx] = 0;         // leave zeroed for next invocation
        }
        run += vals[i];
    }
}

__global__ void scatter_kernel(const int* __restrict__ seq, int n) {
    int t = blockIdx.x * blockDim.x + threadIdx.x;
    int v = 0;
    if (t < n) v = seq[t];           // independent of scan: before sync

    cudaGridDependencySynchronize(); // g_off ready

    if (t < n) {
        int pos = atomicAdd(&g_off[v >> 3], 1);
        g_sorted[pos] = make_int2(v, t);
    }
}

// ---------------- main gather: 64-value vocab ranges ----------------

__global__ __launch_bounds__(THREADS, 8)
void onehot_gather_vrange_kernel(const float* __restrict__ W,
                                 const float* __restrict__ bias,
                                 float* __restrict__ out,
                                 int n_tok, int V) {
    __shared__ float s_w[HCHUNK][SPAD];
    __shared__ int s_o[TBUF];   // value offset within range [0, VRANGE)
    __shared__ int s_t[TBUF];   // original token index

    const int tid   = threadIdx.x;
    const int lane  = tid & 31;
    const int w     = tid >> 5;
    const int k     = blockIdx.x;
    const int vbase = k * VRANGE;

    cudaGridDependencySynchronize();  // g_off/g_sorted ready

    // token slice for this vocab range: buckets 8k .. 8k+7
    const int b0 = k * BPB;
    const int t0 = (k > 0) ? g_off[b0 - 1] : 0;
    const int t1 = g_off[b0 + BPB - 1];

    const size_t Vs = (size_t)V;
    const int v0 = vbase + lane;
    const int v1 = vbase + 32 + lane;
    const bool ok0 = (v0 < V);
    const bool ok1 = (v1 < V);

    for (int tp = t0; tp < t1; tp += TBUF) {  // 1 pass in practice
        const int cnt = min(t1 - tp, TBUF);

        __syncthreads();  // protect s_o/s_t against the previous pass
        for (int j = tid; j < cnt; j += THREADS) {
            int2 vt = g_sorted[tp + j];
            s_o[j] = vt.x - vbase;
            s_t[j] = vt.y;
        }
        __syncthreads();

        for (int c = 0; c < NCHUNK; c++) {
            const int h_base = c * HCHUNK;

            // ---- load: 256B contiguous per h-row (2 coalesced LDGs),
            //      8 rows per warp, MLP = 16 per thread ----
            #pragma unroll
            for (int i = 0; i < 8; i++) {
                int hl = (i << 3) + w;       // warp w covers hl = w, w+8, ...
                const float* Wr = W + (size_t)(h_base + hl) * Vs;
                s_w[hl][lane]      = ok0 ? __ldg(Wr + v0) : 0.0f;
                s_w[hl][32 + lane] = ok1 ? __ldg(Wr + v1) : 0.0f;
            }

            float bl0 = __ldg(bias + h_base + lane);
            float bl1 = __ldg(bias + h_base + 32 + lane);

            __syncthreads();

            // ---- store: warp per token, coalesced 128B rows ----
            for (int j = w; j < cnt; j += 8) {
                const int o = s_o[j];
                float* dst = out + (size_t)s_t[j] * H_DIM + h_base;
                __stcs(dst + lane,      s_w[lane][o]      + bl0);  // stride-65
                __stcs(dst + 32 + lane, s_w[32 + lane][o] + bl1);
            }
            __syncthreads();
        }
    }
}

// ---------------- launch (PDL on the dependency chain) ----------------

template <typename Kern, typename... Args>
static void launch_pdl(Kern k, dim3 grid, dim3 block, Args... args) {
    cudaLaunchConfig_t cfg = {};
    cfg.gridDim  = grid;
    cfg.blockDim = block;
    cfg.dynamicSmemBytes = 0;
    cudaLaunchAttribute attr[1];
    attr[0].id = cudaLaunchAttributeProgrammaticStreamSerialization;
    attr[0].val.programmaticStreamSerializationAllowed = 1;
    cfg.attrs = attr;
    cfg.numAttrs = 1;
    cudaLaunchKernelEx(&cfg, k, args...);
}

extern "C" void kernel_launch(void* const* d_in, const int* in_sizes, int n_in,
                              void* d_out, int out_size) {
    const int*   seq  = (const int*)d_in[0];
    const float* W    = (const float*)d_in[1];
    const float* bias = (const float*)d_in[2];
    float*       out  = (float*)d_out;

    const int n_tok = in_sizes[0];            // 32768
    const int H     = in_sizes[2];            // 1024
    const int V     = in_sizes[1] / H;        // 50257
    const int nbuckets = (V + 7) >> 3;        // 6283
    (void)out_size; (void)n_in;

    hist_kernel<<<(n_tok + 255) / 256, 256>>>(seq, n_tok);

    launch_pdl(scan_kernel, dim3(1), dim3(SCAN_THREADS), nbuckets);
    launch_pdl(scatter_kernel, dim3((n_tok + 255) / 256), dim3(256), seq, n_tok);

    const int vblocks = (V + VRANGE - 1) / VRANGE;  // 786 -> single wave
    launch_pdl(onehot_gather_vrange_kernel, dim3(vblocks), dim3(THREADS),
               W, bias, out, n_tok, V);
}

// round 14
// speedup vs baseline: 1.4098x; 1.1408x over previous
#include <cuda_runtime.h>
#include <cstdint>

// out[t, h] = W[h, seq[t]] + b[h]
// seq: int32 [n_tok], W: fp32 [H, V] row-major, b: fp32 [H], out: fp32 [n_tok, H]
//
// Pipeline (4 launches, ALL PDL):
//  1) hist    : bucket counts of v>>3. PDL launch with NO grid-dependency
//               sync inside -> may run fully concurrent with its stream
//               predecessor, which in steady-state graph replay is the
//               PREVIOUS replay's gather. Safe: hist reads seq / writes
//               g_hist; gather reads g_sorted/W/bias, writes out; g_hist was
//               re-zeroed by the previous replay's scan (2 kernels earlier).
//  2) scan    : syncs on hist; exclusive scan -> g_off; re-zeroes g_hist.
//  3) scatter : reads seq before its sync; counting-sort (v,t) by bucket.
//  4) gather  : R9-proven (52.5us @ 70.7% DRAM): lanes-along-sorted-v loads,
//               padded-SMEM transpose, coalesced streaming stores.

#define H_DIM 1024
#define TOK_PER_BLK 32
#define THREADS 256
#define HCHUNK 128
#define NCHUNK (H_DIM / HCHUNK)   // 8

#define MAX_N 65536
#define MAX_BUCKETS 8192
#define SCAN_THREADS 1024
#define SCAN_PER 8                 // 1024*8 = 8192 >= MAX_BUCKETS

__device__ int g_hist[MAX_BUCKETS];   // zero at load; scan re-zeroes after use
__device__ int g_off[MAX_BUCKETS];
__device__ int2 g_sorted[MAX_N];      // .x = v, .y = t

// ---------------- sort pipeline ----------------

__global__ void hist_kernel(const int* __restrict__ seq, int n) {
    // NO cudaGridDependencySynchronize here: no dependence on the stream
    // predecessor (previous replay's gather) -> full overlap allowed.
    int i = blockIdx.x * blockDim.x + threadIdx.x;
    if (i < n) atomicAdd(&g_hist[seq[i] >> 3], 1);
}

__global__ __launch_bounds__(SCAN_THREADS)
void scan_kernel(int nbuckets) {
    cudaGridDependencySynchronize();   // g_hist ready (waits for hist)

    __shared__ int warp_sums[32];
    const int tid  = threadIdx.x;
    const int lane = tid & 31;
    const int w    = tid >> 5;

    int vals[SCAN_PER];
    int local = 0;
    #pragma unroll
    for (int i = 0; i < SCAN_PER; i++) {
        int idx = tid * SCAN_PER + i;
        vals[i] = (idx < nbuckets) ? g_hist[idx] : 0;
        local += vals[i];
    }

    int x = local;
    #pragma unroll
    for (int d = 1; d < 32; d <<= 1) {
        int y = __shfl_up_sync(0xFFFFFFFFu, x, d);
        if (lane >= d) x += y;
    }
    if (lane == 31) warp_sums[w] = x;
    __syncthreads();

    if (w == 0) {
        int s = warp_sums[lane];
        #pragma unroll
        for (int d = 1; d < 32; d <<= 1) {
            int y = __shfl_up_sync(0xFFFFFFFFu, s, d);
            if (lane >= d) s += y;
        }
        warp_sums[lane] = s;
    }
    __syncthreads();

    int run = (w > 0 ? warp_sums[w - 1] : 0) + (x - local);
    #pragma unroll
    for (int i = 0; i < SCAN_PER; i++) {
        int idx = tid * SCAN_PER + i;
        if (idx < nbuckets) {
            g_off[idx]  = run;
            g_hist[idx] = 0;         // leave zeroed for next invocation
        }
        run += vals[i];
    }
}

__global__ void scatter_kernel(const int* __restrict__ seq, int n) {
    int t = blockIdx.x * blockDim.x + threadIdx.x;
    int v = 0;
    if (t < n) v = seq[t];           // independent of scan: before sync

    cudaGridDependencySynchronize(); // g_off ready

    if (t < n) {
        int pos = atomicAdd(&g_off[v >> 3], 1);
        g_sorted[pos] = make_int2(v, t);
    }
}

// ---------------- main gather (R9-proven body) ----------------

__global__ __launch_bounds__(THREADS, 8)
void onehot_gather_xpose_kernel(const float* __restrict__ W,
                                const float* __restrict__ bias,
                                float* __restrict__ out,
                                int n_tok, int V) {
    __shared__ float s_w[HCHUNK][TOK_PER_BLK + 1];  // pad -> conflict-free both phases
    __shared__ int s_t[TOK_PER_BLK];
    __shared__ int s_v[TOK_PER_BLK];

    const int tid  = threadIdx.x;
    const int lane = tid & 31;
    const int w    = tid >> 5;
    const int base = blockIdx.x * TOK_PER_BLK;

    cudaGridDependencySynchronize();  // g_sorted ready; overlaps block ramp

    if (tid < TOK_PER_BLK) {
        int j = base + tid;
        int2 vt = (j < n_tok) ? g_sorted[j] : make_int2(0, -1);
        s_v[tid] = vt.x;   // clamped: valid address for padding tokens
        s_t[tid] = vt.y;   // -1 -> skip store
    }
    __syncthreads();

    // Load phase: lane owns token 'lane' (sorted values -> few sectors/warp).
    const int my_v = s_v[lane];

    // Store phase: warp w owns tokens 4w..4w+3.
    int st_t[4];
    #pragma unroll
    for (int q = 0; q < 4; q++) st_t[q] = s_t[(w << 2) + q];

    for (int c = 0; c < NCHUNK; c++) {
        const int h_base = c * HCHUNK;

        // ---- load phase: 16 independent gathers per thread ----
        #pragma unroll
        for (int i = 0; i < 16; i++) {
            int h_local = (i << 3) + w;  // warp w covers h_local = w, w+8, ...
            float val = __ldg(W + (size_t)(h_base + h_local) * (size_t)V + my_v);
            s_w[h_local][lane] = val;    // stride-1 across lanes: conflict-free
        }

        // bias for this lane's 4 h positions in the chunk
        float bl[4];
        #pragma unroll
        for (int hs = 0; hs < 4; hs++)
            bl[hs] = __ldg(bias + h_base + (hs << 5) + lane);

        __syncthreads();

        // ---- store phase: coalesced 128B rows ----
        #pragma unroll
        for (int q = 0; q < 4; q++) {
            const int j = (w << 2) + q;
            const int t = st_t[q];
            if (t < 0) continue;
            float* dst = out + (size_t)t * H_DIM + h_base;
            #pragma unroll
            for (int hs = 0; hs < 4; hs++) {
                int h_local = (hs << 5) + lane;
                float r = s_w[h_local][j] + bl[hs];  // stride-33: conflict-free
                __stcs(dst + h_local, r);
            }
        }
        __syncthreads();
    }
}

// ---------------- launch (PDL on the whole chain) ----------------

template <typename Kern, typename... Args>
static void launch_pdl(Kern k, dim3 grid, dim3 block, Args... args) {
    cudaLaunchConfig_t cfg = {};
    cfg.gridDim  = grid;
    cfg.blockDim = block;
    cfg.dynamicSmemBytes = 0;
    cudaLaunchAttribute attr[1];
    attr[0].id = cudaLaunchAttributeProgrammaticStreamSerialization;
    attr[0].val.programmaticStreamSerializationAllowed = 1;
    cfg.attrs = attr;
    cfg.numAttrs = 1;
    cudaLaunchKernelEx(&cfg, k, args...);
}

extern "C" void kernel_launch(void* const* d_in, const int* in_sizes, int n_in,
                              void* d_out, int out_size) {
    const int*   seq  = (const int*)d_in[0];
    const float* W    = (const float*)d_in[1];
    const float* bias = (const float*)d_in[2];
    float*       out  = (float*)d_out;

    const int n_tok = in_sizes[0];            // 32768
    const int H     = in_sizes[2];            // 1024
    const int V     = in_sizes[1] / H;        // 50257
    const int nbuckets = (V + 7) >> 3;        // 6283
    (void)out_size; (void)n_in;

    // hist: PDL + no internal sync -> may fully overlap the previous
    // replay's gather (steady-state graph timing).
    launch_pdl(hist_kernel, dim3((n_tok + 255) / 256), dim3(256), seq, n_tok);

    launch_pdl(scan_kernel, dim3(1), dim3(SCAN_THREADS), nbuckets);
    launch_pdl(scatter_kernel, dim3((n_tok + 255) / 256), dim3(256), seq, n_tok);

    const int blocks = (n_tok + TOK_PER_BLK - 1) / TOK_PER_BLK;
    launch_pdl(onehot_gather_xpose_kernel, dim3(blocks), dim3(THREADS),
               W, bias, out, n_tok, V);
}